// round 11
// baseline (speedup 1.0000x reference)
#include <cuda_runtime.h>
#include <cstdint>

#define BATCH 32
#define CIN   256
#define HW    3136          // 56*56
#define HWQ   784           // HW/4
#define CR    8
#define NPIX  (BATCH*HW)    // 100352
#define NQUAD (NPIX/4)      // 25088
#define COUT  44            // 8 + 36

#define KS    4             // K-splits
#define CPK   (CIN/KS)      // 64 channels per split
#define QPB   64            // pixel-quads per block (256 thr = 64 quads * 4 splits)
#define SRSTR 18            // padded row stride (u64) for partials

// z buffer, pixel-major: [b][p][c], 32B per pixel record
__device__ float g_z[NPIX*CR];

typedef unsigned long long u64;

__device__ __forceinline__ u64 fma2(u64 a, u64 b, u64 c) {
    u64 d;
    asm("fma.rn.f32x2 %0, %1, %2, %3;" : "=l"(d) : "l"(a), "l"(b), "l"(c));
    return d;
}
__device__ __forceinline__ u64 add2(u64 a, u64 b) {
    u64 d;
    asm("add.rn.f32x2 %0, %1, %2;" : "=l"(d) : "l"(a), "l"(b));
    return d;
}
__device__ __forceinline__ u64 pack2(float lo, float hi) {
    u64 r;
    asm("mov.b64 %0, {%1, %2};" : "=l"(r) : "f"(lo), "f"(hi));
    return r;
}
__device__ __forceinline__ float2 unpack2(u64 v) {
    float2 r;
    asm("mov.b64 {%0, %1}, %2;" : "=f"(r.x), "=f"(r.y) : "l"(v));
    return r;
}

__device__ __forceinline__ void quad_fma(u64* aL, u64* aH,
                                         const u64* swrow, ulonglong2 xv) {
    const ulonglong2* wrow = reinterpret_cast<const ulonglong2*>(swrow);
    ulonglong2 w01 = wrow[0], w23 = wrow[1], w45 = wrow[2], w67 = wrow[3];
    aL[0]=fma2(w01.x,xv.x,aL[0]); aH[0]=fma2(w01.x,xv.y,aH[0]);
    aL[1]=fma2(w01.y,xv.x,aL[1]); aH[1]=fma2(w01.y,xv.y,aH[1]);
    aL[2]=fma2(w23.x,xv.x,aL[2]); aH[2]=fma2(w23.x,xv.y,aH[2]);
    aL[3]=fma2(w23.y,xv.x,aL[3]); aH[3]=fma2(w23.y,xv.y,aH[3]);
    aL[4]=fma2(w45.x,xv.x,aL[4]); aH[4]=fma2(w45.x,xv.y,aH[4]);
    aL[5]=fma2(w45.y,xv.x,aL[5]); aH[5]=fma2(w45.y,xv.y,aH[5]);
    aL[6]=fma2(w67.x,xv.x,aL[6]); aH[6]=fma2(w67.x,xv.y,aH[6]);
    aL[7]=fma2(w67.y,xv.x,aL[7]); aH[7]=fma2(w67.y,xv.y,aH[7]);
}

// ============================================================
// 1x1 conv + BN(folded) + ReLU. LDG.128 (4px/thread), K-split x4,
// 3-stage pipelined loads (12 LDG.128 in flight / thread).
// grid = NQUAD/QPB = 392 blocks * 256 thr   (R5 structure)
// ============================================================
__global__ void __launch_bounds__(256) conv1x1_k(const float* __restrict__ x,
                                                 const float* __restrict__ wr,
                                                 const float* __restrict__ gamma,
                                                 const float* __restrict__ beta,
                                                 const float* __restrict__ mean,
                                                 const float* __restrict__ var) {
    __shared__ u64   sw[CIN*CR];            // 16 KB folded duplicated weights
    __shared__ u64   sred[KS*QPB*SRSTR];    // 36 KB padded partials
    __shared__ float sinv[CR], sbias[CR];

    if (threadIdx.x < CR) {
        int c = threadIdx.x;
        float inv = gamma[c] * rsqrtf(var[c] + 1e-5f);
        sinv[c]  = inv;
        sbias[c] = beta[c] - mean[c] * inv;
    }
    __syncthreads();
    #pragma unroll
    for (int i = threadIdx.x; i < CIN*CR; i += 256) {
        int ci = i >> 3;
        int c  = i & 7;
        float w = wr[c*CIN + ci] * sinv[c];
        sw[i] = pack2(w, w);
    }
    __syncthreads();

    int lq = threadIdx.x & (QPB-1);      // quad within block
    int ks = threadIdx.x >> 6;           // k-split 0..3
    int qq = blockIdx.x * QPB + lq;      // global quad index, exact coverage
    int b  = qq / HWQ;
    int qi = qq % HWQ;

    const ulonglong2* xp = reinterpret_cast<const ulonglong2*>(x)
                         + (size_t)b*CIN*HWQ + (size_t)(ks*CPK)*HWQ + qi;
    const u64* swb = &sw[ks*CPK*CR];

    u64 aL[CR], aH[CR];                  // accum: px{0,1} and px{2,3}
    #pragma unroll
    for (int c = 0; c < CR; c++) { aL[c] = 0ull; aH[c] = 0ull; }

    // 16 groups of 4 channels; 3 slots: load group g+2 before computing g
    ulonglong2 xs[3][4];
    #pragma unroll
    for (int g0 = 0; g0 < 2; g0++)
        #pragma unroll
        for (int u = 0; u < 4; u++)
            xs[g0][u] = xp[(size_t)(g0*4+u)*HWQ];

    #pragma unroll 1
    for (int g = 0; g < 16; g++) {
        int slot = g % 3;
        if (g + 2 < 16) {
            int ns = (g + 2) % 3;
            #pragma unroll
            for (int u = 0; u < 4; u++)
                xs[ns][u] = xp[(size_t)((g+2)*4+u)*HWQ];
        }
        #pragma unroll
        for (int u = 0; u < 4; u++)
            quad_fma(aL, aH, &swb[(g*4+u)*CR], xs[slot][u]);
    }

    // stash 16 partials (i=c for px01, 8+c for px23), padded rows
    {
        u64* row = &sred[(size_t)(ks*QPB + lq)*SRSTR];
        ulonglong2* r2 = reinterpret_cast<ulonglong2*>(row);
        #pragma unroll
        for (int j = 0; j < 4; j++) r2[j]   = make_ulonglong2(aL[2*j], aL[2*j+1]);
        #pragma unroll
        for (int j = 0; j < 4; j++) r2[4+j] = make_ulonglong2(aH[2*j], aH[2*j+1]);
    }
    __syncthreads();

    // all 256 threads: each reduces 4 consecutive outputs of one quad
    {
        int t   = threadIdx.x;
        int lq2 = t >> 2;                 // quad handled
        int m   = t & 3;                  // which 4-output group
        int i0  = m * 4;
        int pairp = m >> 1;               // 0: px{0,1}, 1: px{2,3}
        int half  = m & 1;                // channels half*4..
        u64 s[4];
        #pragma unroll
        for (int j = 0; j < 4; j++) s[j] = 0ull;
        #pragma unroll
        for (int k = 0; k < KS; k++) {
            const ulonglong2* r2 = reinterpret_cast<const ulonglong2*>(
                &sred[(size_t)(k*QPB + lq2)*SRSTR + i0]);
            ulonglong2 p0 = r2[0], p1 = r2[1];
            s[0] = add2(s[0], p0.x); s[1] = add2(s[1], p0.y);
            s[2] = add2(s[2], p1.x); s[3] = add2(s[3], p1.y);
        }
        int qq2 = blockIdx.x * QPB + lq2;
        int b2  = qq2 / HWQ;
        int qi2 = qq2 % HWQ;
        float lo[4], hi[4];
        #pragma unroll
        for (int j = 0; j < 4; j++) {
            float2 v = unpack2(s[j]);
            float bia = sbias[half*4 + j];
            lo[j] = fmaxf(v.x + bia, 0.f);
            hi[j] = fmaxf(v.y + bia, 0.f);
        }
        int P0 = qi2*4 + pairp*2;
        float4* z0 = reinterpret_cast<float4*>(
            g_z + ((size_t)b2*HW + P0)*CR + half*4);
        float4* z1 = reinterpret_cast<float4*>(
            g_z + ((size_t)b2*HW + P0 + 1)*CR + half*4);
        *z0 = make_float4(lo[0], lo[1], lo[2], lo[3]);
        *z1 = make_float4(hi[0], hi[1], hi[2], hi[3]);
    }
}

// ============================================================
// Depthwise 3x3 (scale folded) + L2-norms + pairwise products.
// R7 version verbatim (best measured: 8.7 us).
// grid = 32 images x 14 bands = 448 blocks of 224 threads.
// ============================================================
#define TW 58
__global__ void __launch_bounds__(224) twist_k(float* __restrict__ out,
                                               const float* __restrict__ wdw,
                                               const float* __restrict__ scale) {
    __shared__ float4 sA[6*TW];
    __shared__ float4 sC[6*TW];
    __shared__ float  swd[CR*9];

    int tid = threadIdx.x;
    if (tid < CR*9) swd[tid] = wdw[tid] * scale[tid/9];

    int b    = blockIdx.x / 14;
    int band = blockIdx.x - b*14;
    int y0   = band * 4;

    const float4* zb = reinterpret_cast<const float4*>(g_z) + (size_t)b*HW*2;

    for (int f = tid; f < 6*TW; f += 224) {
        int r  = f / TW;
        int c  = f - r*TW;
        int gy = y0 + r - 1;
        int gx = c - 1;
        float4 va = make_float4(0.f,0.f,0.f,0.f);
        float4 vc = va;
        if ((unsigned)gy < 56u && (unsigned)gx < 56u) {
            size_t q = (size_t)(gy*56 + gx)*2;
            va = __ldg(&zb[q]);
            vc = __ldg(&zb[q+1]);
        }
        sA[f] = va;
        sC[f] = vc;
    }
    __syncthreads();

    int row = tid / 56;                 // 0..3
    int col = tid - row*56;             // 0..55
    int s0  = (row+1)*TW + (col+1);     // center index

    float zc[CR], t[CR];
    {
        float4 a = sA[s0];
        float4 c = sC[s0];
        zc[0]=a.x; zc[1]=a.y; zc[2]=a.z; zc[3]=a.w;
        zc[4]=c.x; zc[5]=c.y; zc[6]=c.z; zc[7]=c.w;
    }
    #pragma unroll
    for (int c = 0; c < CR; c++) t[c] = 0.f;

    #pragma unroll
    for (int dy = -1; dy <= 1; dy++) {
        #pragma unroll
        for (int dx = -1; dx <= 1; dx++) {
            int si = s0 + dy*TW + dx;
            int k  = (dy+1)*3 + (dx+1);
            float4 a = sA[si];
            float4 c = sC[si];
            t[0] = fmaf(a.x, swd[0*9+k], t[0]);
            t[1] = fmaf(a.y, swd[1*9+k], t[1]);
            t[2] = fmaf(a.z, swd[2*9+k], t[2]);
            t[3] = fmaf(a.w, swd[3*9+k], t[3]);
            t[4] = fmaf(c.x, swd[4*9+k], t[4]);
            t[5] = fmaf(c.y, swd[5*9+k], t[5]);
            t[6] = fmaf(c.z, swd[6*9+k], t[6]);
            t[7] = fmaf(c.w, swd[7*9+k], t[7]);
        }
    }

    float s2z = 0.f, s2t = 0.f;
    #pragma unroll
    for (int c = 0; c < CR; c++) { s2z = fmaf(zc[c], zc[c], s2z); s2t = fmaf(t[c], t[c], s2t); }
    float iz = 1.0f / fmaxf(sqrtf(s2z), 1e-6f);
    float it = 1.0f / fmaxf(sqrtf(s2t), 1e-6f);

    float zn[CR], tn[CR];
    #pragma unroll
    for (int c = 0; c < CR; c++) { zn[c] = zc[c]*iz; tn[c] = t[c]*it; }

    int p = (y0 + row)*56 + col;
    float* ob = out + (size_t)b*COUT*HW + p;
    #pragma unroll
    for (int c = 0; c < CR; c++) ob[(size_t)c*HW] = zn[c];

    int k = 8;
    #pragma unroll
    for (int i = 0; i < CR; i++) {
        #pragma unroll
        for (int j = i; j < CR; j++) {
            ob[(size_t)k*HW] = zn[i]*tn[j];
            k++;
        }
    }
}

// ============================================================
extern "C" void kernel_launch(void* const* d_in, const int* in_sizes, int n_in,
                              void* d_out, int out_size) {
    const float* x     = (const float*)d_in[0];
    const float* wr    = (const float*)d_in[1];
    const float* gamma = (const float*)d_in[2];
    const float* beta  = (const float*)d_in[3];
    const float* mean  = (const float*)d_in[4];
    const float* var   = (const float*)d_in[5];
    const float* wdw   = (const float*)d_in[6];
    const float* scale = (const float*)d_in[7];
    float* out = (float*)d_out;

    conv1x1_k<<<NQUAD/QPB, 256>>>(x, wr, gamma, beta, mean, var);
    twist_k<<<BATCH*14, 224>>>(out, wdw, scale);
}

// round 12
// speedup vs baseline: 1.1816x; 1.1816x over previous
#include <cuda_runtime.h>
#include <cstdint>

#define BATCH 32
#define CIN   256
#define HW    3136          // 56*56
#define HWQ   784           // HW/4
#define CR    8
#define NPIX  (BATCH*HW)    // 100352
#define NQUAD (NPIX/4)      // 25088
#define COUT  44            // 8 + 36

#define KS    4             // K-splits
#define CPK   (CIN/KS)      // 64 channels per split
#define QPB   64            // pixel-quads per block (256 thr = 64 quads * 4 splits)
#define SRSTR 18            // padded row stride (u64) for partials

// z buffer, pixel-major: [b][p][c], 32B per pixel record
__device__ float g_z[NPIX*CR];

typedef unsigned long long u64;

__device__ __forceinline__ u64 fma2(u64 a, u64 b, u64 c) {
    u64 d;
    asm("fma.rn.f32x2 %0, %1, %2, %3;" : "=l"(d) : "l"(a), "l"(b), "l"(c));
    return d;
}
__device__ __forceinline__ u64 add2(u64 a, u64 b) {
    u64 d;
    asm("add.rn.f32x2 %0, %1, %2;" : "=l"(d) : "l"(a), "l"(b));
    return d;
}
__device__ __forceinline__ u64 pack2(float lo, float hi) {
    u64 r;
    asm("mov.b64 %0, {%1, %2};" : "=l"(r) : "f"(lo), "f"(hi));
    return r;
}
__device__ __forceinline__ float2 unpack2(u64 v) {
    float2 r;
    asm("mov.b64 {%0, %1}, %2;" : "=f"(r.x), "=f"(r.y) : "l"(v));
    return r;
}

// ============================================================
// 1x1 conv + BN(folded) + ReLU. LDG.128 (4px/thread), K-split x4,
// 2-stage pipelined loads with STATIC double buffers (R5, measured
// best: ~24.5us). grid = NQUAD/QPB = 392 blocks * 256 thr
// ============================================================
__global__ void __launch_bounds__(256) conv1x1_k(const float* __restrict__ x,
                                                 const float* __restrict__ wr,
                                                 const float* __restrict__ gamma,
                                                 const float* __restrict__ beta,
                                                 const float* __restrict__ mean,
                                                 const float* __restrict__ var) {
    __shared__ u64   sw[CIN*CR];            // 16 KB folded duplicated weights
    __shared__ u64   sred[KS*QPB*SRSTR];    // 36 KB padded partials
    __shared__ float sinv[CR], sbias[CR];

    if (threadIdx.x < CR) {
        int c = threadIdx.x;
        float inv = gamma[c] * rsqrtf(var[c] + 1e-5f);
        sinv[c]  = inv;
        sbias[c] = beta[c] - mean[c] * inv;
    }
    __syncthreads();
    #pragma unroll
    for (int i = threadIdx.x; i < CIN*CR; i += 256) {
        int ci = i >> 3;
        int c  = i & 7;
        float w = wr[c*CIN + ci] * sinv[c];
        sw[i] = pack2(w, w);
    }
    __syncthreads();

    int lq = threadIdx.x & (QPB-1);      // quad within block
    int ks = threadIdx.x >> 6;           // k-split 0..3
    int qq = blockIdx.x * QPB + lq;      // global quad index, exact coverage
    int b  = qq / HWQ;
    int qi = qq % HWQ;

    const ulonglong2* xp = reinterpret_cast<const ulonglong2*>(x)
                         + (size_t)b*CIN*HWQ + (size_t)(ks*CPK)*HWQ + qi;
    const u64* swb = &sw[ks*CPK*CR];

    u64 aL[CR], aH[CR];                  // accum: px{0,1} and px{2,3}
    #pragma unroll
    for (int c = 0; c < CR; c++) { aL[c] = 0ull; aH[c] = 0ull; }

    ulonglong2 xa[4], xb[4];
    #pragma unroll
    for (int u = 0; u < 4; u++) xa[u] = xp[(size_t)u*HWQ];

    #pragma unroll 1
    for (int ci = 0; ci < CPK; ci += 8) {
        #pragma unroll
        for (int u = 0; u < 4; u++) xb[u] = xp[(size_t)(ci+4+u)*HWQ];
        #pragma unroll
        for (int u = 0; u < 4; u++) {
            const ulonglong2* wrow =
                reinterpret_cast<const ulonglong2*>(&swb[(ci+u)*CR]);
            ulonglong2 w01 = wrow[0], w23 = wrow[1], w45 = wrow[2], w67 = wrow[3];
            ulonglong2 xv = xa[u];
            aL[0]=fma2(w01.x,xv.x,aL[0]); aH[0]=fma2(w01.x,xv.y,aH[0]);
            aL[1]=fma2(w01.y,xv.x,aL[1]); aH[1]=fma2(w01.y,xv.y,aH[1]);
            aL[2]=fma2(w23.x,xv.x,aL[2]); aH[2]=fma2(w23.x,xv.y,aH[2]);
            aL[3]=fma2(w23.y,xv.x,aL[3]); aH[3]=fma2(w23.y,xv.y,aH[3]);
            aL[4]=fma2(w45.x,xv.x,aL[4]); aH[4]=fma2(w45.x,xv.y,aH[4]);
            aL[5]=fma2(w45.y,xv.x,aL[5]); aH[5]=fma2(w45.y,xv.y,aH[5]);
            aL[6]=fma2(w67.x,xv.x,aL[6]); aH[6]=fma2(w67.x,xv.y,aH[6]);
            aL[7]=fma2(w67.y,xv.x,aL[7]); aH[7]=fma2(w67.y,xv.y,aH[7]);
        }
        if (ci + 8 < CPK) {
            #pragma unroll
            for (int u = 0; u < 4; u++) xa[u] = xp[(size_t)(ci+8+u)*HWQ];
        }
        #pragma unroll
        for (int u = 0; u < 4; u++) {
            const ulonglong2* wrow =
                reinterpret_cast<const ulonglong2*>(&swb[(ci+4+u)*CR]);
            ulonglong2 w01 = wrow[0], w23 = wrow[1], w45 = wrow[2], w67 = wrow[3];
            ulonglong2 xv = xb[u];
            aL[0]=fma2(w01.x,xv.x,aL[0]); aH[0]=fma2(w01.x,xv.y,aH[0]);
            aL[1]=fma2(w01.y,xv.x,aL[1]); aH[1]=fma2(w01.y,xv.y,aH[1]);
            aL[2]=fma2(w23.x,xv.x,aL[2]); aH[2]=fma2(w23.x,xv.y,aH[2]);
            aL[3]=fma2(w23.y,xv.x,aL[3]); aH[3]=fma2(w23.y,xv.y,aH[3]);
            aL[4]=fma2(w45.x,xv.x,aL[4]); aH[4]=fma2(w45.x,xv.y,aH[4]);
            aL[5]=fma2(w45.y,xv.x,aL[5]); aH[5]=fma2(w45.y,xv.y,aH[5]);
            aL[6]=fma2(w67.x,xv.x,aL[6]); aH[6]=fma2(w67.x,xv.y,aH[6]);
            aL[7]=fma2(w67.y,xv.x,aL[7]); aH[7]=fma2(w67.y,xv.y,aH[7]);
        }
    }

    // stash 16 partials (i=c for px01, 8+c for px23), padded rows
    {
        u64* row = &sred[(size_t)(ks*QPB + lq)*SRSTR];
        ulonglong2* r2 = reinterpret_cast<ulonglong2*>(row);
        #pragma unroll
        for (int j = 0; j < 4; j++) r2[j]   = make_ulonglong2(aL[2*j], aL[2*j+1]);
        #pragma unroll
        for (int j = 0; j < 4; j++) r2[4+j] = make_ulonglong2(aH[2*j], aH[2*j+1]);
    }
    __syncthreads();

    // all 256 threads: each reduces 4 consecutive outputs of one quad
    {
        int t   = threadIdx.x;
        int lq2 = t >> 2;                 // quad handled
        int m   = t & 3;                  // which 4-output group
        int i0  = m * 4;
        int pairp = m >> 1;               // 0: px{0,1}, 1: px{2,3}
        int half  = m & 1;                // channels half*4..
        u64 s[4];
        #pragma unroll
        for (int j = 0; j < 4; j++) s[j] = 0ull;
        #pragma unroll
        for (int k = 0; k < KS; k++) {
            const ulonglong2* r2 = reinterpret_cast<const ulonglong2*>(
                &sred[(size_t)(k*QPB + lq2)*SRSTR + i0]);
            ulonglong2 p0 = r2[0], p1 = r2[1];
            s[0] = add2(s[0], p0.x); s[1] = add2(s[1], p0.y);
            s[2] = add2(s[2], p1.x); s[3] = add2(s[3], p1.y);
        }
        int qq2 = blockIdx.x * QPB + lq2;
        int b2  = qq2 / HWQ;
        int qi2 = qq2 % HWQ;
        float lo[4], hi[4];
        #pragma unroll
        for (int j = 0; j < 4; j++) {
            float2 v = unpack2(s[j]);
            float bia = sbias[half*4 + j];
            lo[j] = fmaxf(v.x + bia, 0.f);
            hi[j] = fmaxf(v.y + bia, 0.f);
        }
        int P0 = qi2*4 + pairp*2;
        float4* z0 = reinterpret_cast<float4*>(
            g_z + ((size_t)b2*HW + P0)*CR + half*4);
        float4* z1 = reinterpret_cast<float4*>(
            g_z + ((size_t)b2*HW + P0 + 1)*CR + half*4);
        *z0 = make_float4(lo[0], lo[1], lo[2], lo[3]);
        *z1 = make_float4(hi[0], hi[1], hi[2], hi[3]);
    }
}

// ============================================================
// Depthwise 3x3 (scale folded) + L2-norms + pairwise products.
// R7 version verbatim (best measured: 8.3-8.7 us).
// grid = 32 images x 14 bands = 448 blocks of 224 threads.
// ============================================================
#define TW 58
__global__ void __launch_bounds__(224) twist_k(float* __restrict__ out,
                                               const float* __restrict__ wdw,
                                               const float* __restrict__ scale) {
    __shared__ float4 sA[6*TW];
    __shared__ float4 sC[6*TW];
    __shared__ float  swd[CR*9];

    int tid = threadIdx.x;
    if (tid < CR*9) swd[tid] = wdw[tid] * scale[tid/9];

    int b    = blockIdx.x / 14;
    int band = blockIdx.x - b*14;
    int y0   = band * 4;

    const float4* zb = reinterpret_cast<const float4*>(g_z) + (size_t)b*HW*2;

    for (int f = tid; f < 6*TW; f += 224) {
        int r  = f / TW;
        int c  = f - r*TW;
        int gy = y0 + r - 1;
        int gx = c - 1;
        float4 va = make_float4(0.f,0.f,0.f,0.f);
        float4 vc = va;
        if ((unsigned)gy < 56u && (unsigned)gx < 56u) {
            size_t q = (size_t)(gy*56 + gx)*2;
            va = __ldg(&zb[q]);
            vc = __ldg(&zb[q+1]);
        }
        sA[f] = va;
        sC[f] = vc;
    }
    __syncthreads();

    int row = tid / 56;                 // 0..3
    int col = tid - row*56;             // 0..55
    int s0  = (row+1)*TW + (col+1);     // center index

    float zc[CR], t[CR];
    {
        float4 a = sA[s0];
        float4 c = sC[s0];
        zc[0]=a.x; zc[1]=a.y; zc[2]=a.z; zc[3]=a.w;
        zc[4]=c.x; zc[5]=c.y; zc[6]=c.z; zc[7]=c.w;
    }
    #pragma unroll
    for (int c = 0; c < CR; c++) t[c] = 0.f;

    #pragma unroll
    for (int dy = -1; dy <= 1; dy++) {
        #pragma unroll
        for (int dx = -1; dx <= 1; dx++) {
            int si = s0 + dy*TW + dx;
            int k  = (dy+1)*3 + (dx+1);
            float4 a = sA[si];
            float4 c = sC[si];
            t[0] = fmaf(a.x, swd[0*9+k], t[0]);
            t[1] = fmaf(a.y, swd[1*9+k], t[1]);
            t[2] = fmaf(a.z, swd[2*9+k], t[2]);
            t[3] = fmaf(a.w, swd[3*9+k], t[3]);
            t[4] = fmaf(c.x, swd[4*9+k], t[4]);
            t[5] = fmaf(c.y, swd[5*9+k], t[5]);
            t[6] = fmaf(c.z, swd[6*9+k], t[6]);
            t[7] = fmaf(c.w, swd[7*9+k], t[7]);
        }
    }

    float s2z = 0.f, s2t = 0.f;
    #pragma unroll
    for (int c = 0; c < CR; c++) { s2z = fmaf(zc[c], zc[c], s2z); s2t = fmaf(t[c], t[c], s2t); }
    float iz = 1.0f / fmaxf(sqrtf(s2z), 1e-6f);
    float it = 1.0f / fmaxf(sqrtf(s2t), 1e-6f);

    float zn[CR], tn[CR];
    #pragma unroll
    for (int c = 0; c < CR; c++) { zn[c] = zc[c]*iz; tn[c] = t[c]*it; }

    int p = (y0 + row)*56 + col;
    float* ob = out + (size_t)b*COUT*HW + p;
    #pragma unroll
    for (int c = 0; c < CR; c++) ob[(size_t)c*HW] = zn[c];

    int k = 8;
    #pragma unroll
    for (int i = 0; i < CR; i++) {
        #pragma unroll
        for (int j = i; j < CR; j++) {
            ob[(size_t)k*HW] = zn[i]*tn[j];
            k++;
        }
    }
}

// ============================================================
extern "C" void kernel_launch(void* const* d_in, const int* in_sizes, int n_in,
                              void* d_out, int out_size) {
    const float* x     = (const float*)d_in[0];
    const float* wr    = (const float*)d_in[1];
    const float* gamma = (const float*)d_in[2];
    const float* beta  = (const float*)d_in[3];
    const float* mean  = (const float*)d_in[4];
    const float* var   = (const float*)d_in[5];
    const float* wdw   = (const float*)d_in[6];
    const float* scale = (const float*)d_in[7];
    float* out = (float*)d_out;

    conv1x1_k<<<NQUAD/QPB, 256>>>(x, wr, gamma, beta, mean, var);
    twist_k<<<BATCH*14, 224>>>(out, wdw, scale);
}